// round 1
// baseline (speedup 1.0000x reference)
#include <cuda_runtime.h>
#include <cstdint>
#include <math.h>

#define H      1024
#define E      16
#define T      8192
#define TOPK   6
#define EPSV   1e-10f

#define BM 128
#define BN 128
#define BK 16
#define APAD 20    // BK+4 stride for A smem (conflict-free frag loads)
#define BPAD 132   // BN+4 stride for B smem
#define NKIT (H/BK)

// ---- scratch (device globals; no allocation allowed) ----
__device__ int   d_counts[E];
__device__ int   d_perm_token[E*T];
__device__ int   d_perm_dest [E*T];
__device__ float d_perm_coef [E*T];
__device__ float d_bias[T];
__device__ float d_scratch[(size_t)T*TOPK*H];   // 192 MB: per-(token,rank) GEMM rows

// ============================================================
__global__ void zero_counts_kernel() {
    if (threadIdx.x < E) d_counts[threadIdx.x] = 0;
}

// ============================================================
// Router: warp per token. Computes logits, softmax, top-6, coefficients,
// and scatters token assignments into per-expert lists.
__global__ void __launch_bounds__(256) router_kernel(
    const float* __restrict__ tokens,
    const float* __restrict__ rw,
    const float* __restrict__ rb)
{
    const int warp = threadIdx.x >> 5;
    const int lane = threadIdx.x & 31;

    for (int it = 0; it < 16; ++it) {
        const int t = blockIdx.x * 128 + warp * 16 + it;

        // load x row into registers (coalesced)
        float xr[32];
        const float* xp = tokens + (size_t)t * H;
        #pragma unroll
        for (int j = 0; j < 32; ++j) xr[j] = xp[j * 32 + lane];

        // 16 dot products; lane e ends up holding logit_e
        float myLogit = -INFINITY;
        #pragma unroll
        for (int e = 0; e < E; ++e) {
            const float* wp = rw + e * H;
            float s = 0.f;
            #pragma unroll
            for (int j = 0; j < 32; ++j) s += xr[j] * wp[j * 32 + lane];
            #pragma unroll
            for (int o = 16; o; o >>= 1) s += __shfl_xor_sync(0xffffffffu, s, o);
            if (lane == e) myLogit = s + rb[e];
        }

        // softmax over lanes 0..15
        float m = myLogit;
        #pragma unroll
        for (int o = 16; o; o >>= 1) m = fmaxf(m, __shfl_xor_sync(0xffffffffu, m, o));
        float p = (lane < E) ? expf(myLogit - m) : 0.f;
        float Z = p;
        #pragma unroll
        for (int o = 16; o; o >>= 1) Z += __shfl_xor_sync(0xffffffffu, Z, o);

        // gather all 16 (unnormalized) probs to lane 0
        float pv[E];
        #pragma unroll
        for (int e = 0; e < E; ++e) {
            float v = __shfl_sync(0xffffffffu, p, e);
            pv[e] = v;
        }

        if (lane == 0) {
            int   ids[TOPK];
            float ps [TOPK];
            float s = 0.f;
            #pragma unroll
            for (int k = 0; k < TOPK; ++k) {
                int best = 0; float bv = pv[0];
                #pragma unroll
                for (int e = 1; e < E; ++e)
                    if (pv[e] > bv) { bv = pv[e]; best = e; }
                ids[k] = best; ps[k] = bv; pv[best] = -1.f; s += bv;
            }
            // effective coefficient per expert = p_k / sum(top6 p)   (EPS cancels)
            #pragma unroll
            for (int k = 0; k < TOPK; ++k) {
                const float coef = ps[k] / s;
                const int e = ids[k];
                const int pos = atomicAdd(&d_counts[e], 1);
                d_perm_token[e * T + pos] = t;
                d_perm_dest [e * T + pos] = t * TOPK + k;
                d_perm_coef [e * T + pos] = coef;
            }
            // dummy gradient term: EPS * sum(renormalized top-k) = EPS * s_n/(s_n+EPS)
            const float sn = s / Z;
            d_bias[t] = EPSV * sn / (sn + EPSV);
        }
    }
}

// ============================================================
__device__ __forceinline__ unsigned f2tf(float f) {
    unsigned r;
    asm("cvt.rna.tf32.f32 %0, %1;" : "=r"(r) : "f"(f));
    return r;
}

// Grouped GEMM: per-expert gathered rows, TF32 mma.sync, fp32 accumulate.
// Grid: (H/BN, T/BM, E). Blocks past the expert's token count exit early.
__global__ void __launch_bounds__(256) moe_gemm_kernel(
    const float* __restrict__ x,
    const float* __restrict__ ew)
{
    const int e     = blockIdx.z;
    const int cnt   = d_counts[e];
    const int mBase = blockIdx.y * BM;
    if (mBase >= cnt) return;
    const int nBase = blockIdx.x * BN;

    const float* Wp   = ew + (size_t)e * H * H;      // [K=H, N=H] row-major
    const int*   ptok = d_perm_token + e * T;

    __shared__ unsigned Asm[2][BM][APAD];
    __shared__ unsigned Bsm[2][BK][BPAD];

    const int tid  = threadIdx.x;
    const int lane = tid & 31;
    const int warp = tid >> 5;
    const int wm   = warp >> 1;   // 0..3  (32 rows each)
    const int wn   = warp & 1;    // 0..1  (64 cols each)

    // ---- global pointers (per-thread, fixed rows across K loop) ----
    const float* ap[2];
    int am_m[2], am_kg[2];
    #pragma unroll
    for (int i = 0; i < 2; ++i) {
        const int idx = tid + i * 256;
        const int m = idx >> 2, kg = idx & 3;
        am_m[i] = m; am_kg[i] = kg;
        const int gm = mBase + m;
        const int tok = (gm < cnt) ? ptok[gm] : 0;   // clamped rows never stored
        ap[i] = x + (size_t)tok * H + kg * 4;
    }
    const int bn4 = tid & 31;
    const float* bp[2];
    int bk_[2];
    #pragma unroll
    for (int i = 0; i < 2; ++i) {
        const int k = (tid + i * 256) >> 5;
        bk_[i] = k;
        bp[i] = Wp + (size_t)k * H + nBase + bn4 * 4;
    }

    float4 ra[2], rbv[2];
    #pragma unroll
    for (int i = 0; i < 2; ++i) {
        ra [i] = *(const float4*)(ap[i]);
        rbv[i] = *(const float4*)(bp[i]);
    }

    // stage registers -> smem (with RNA rounding to tf32)
    auto stage = [&](int buf) {
        #pragma unroll
        for (int i = 0; i < 2; ++i) {
            unsigned* da = &Asm[buf][am_m[i]][am_kg[i] * 4];
            da[0] = f2tf(ra[i].x); da[1] = f2tf(ra[i].y);
            da[2] = f2tf(ra[i].z); da[3] = f2tf(ra[i].w);
            unsigned* db = &Bsm[buf][bk_[i]][bn4 * 4];
            db[0] = f2tf(rbv[i].x); db[1] = f2tf(rbv[i].y);
            db[2] = f2tf(rbv[i].z); db[3] = f2tf(rbv[i].w);
        }
    };
    stage(0);
    __syncthreads();

    float c[2][8][4];
    #pragma unroll
    for (int mt = 0; mt < 2; ++mt)
        #pragma unroll
        for (int nt = 0; nt < 8; ++nt)
            #pragma unroll
            for (int q = 0; q < 4; ++q) c[mt][nt][q] = 0.f;

    for (int kt = 0; kt < NKIT; ++kt) {
        const int buf = kt & 1;
        if (kt + 1 < NKIT) {
            #pragma unroll
            for (int i = 0; i < 2; ++i) {
                ra [i] = *(const float4*)(ap[i] + (kt + 1) * BK);
                rbv[i] = *(const float4*)(bp[i] + (size_t)(kt + 1) * BK * H);
            }
        }
        #pragma unroll
        for (int ks = 0; ks < 2; ++ks) {
            unsigned a[2][4], b[8][2];
            const int kcol = ks * 8 + (lane & 3);
            #pragma unroll
            for (int mt = 0; mt < 2; ++mt) {
                const int r = wm * 32 + mt * 16 + (lane >> 2);
                a[mt][0] = Asm[buf][r    ][kcol    ];
                a[mt][1] = Asm[buf][r + 8][kcol    ];
                a[mt][2] = Asm[buf][r    ][kcol + 4];
                a[mt][3] = Asm[buf][r + 8][kcol + 4];
            }
            #pragma unroll
            for (int nt = 0; nt < 8; ++nt) {
                const int ncol = wn * 64 + nt * 8 + (lane >> 2);
                b[nt][0] = Bsm[buf][kcol    ][ncol];
                b[nt][1] = Bsm[buf][kcol + 4][ncol];
            }
            #pragma unroll
            for (int mt = 0; mt < 2; ++mt)
                #pragma unroll
                for (int nt = 0; nt < 8; ++nt)
                    asm volatile(
                        "mma.sync.aligned.m16n8k8.row.col.f32.tf32.tf32.f32 "
                        "{%0,%1,%2,%3}, {%4,%5,%6,%7}, {%8,%9}, {%0,%1,%2,%3};\n"
                        : "+f"(c[mt][nt][0]), "+f"(c[mt][nt][1]),
                          "+f"(c[mt][nt][2]), "+f"(c[mt][nt][3])
                        : "r"(a[mt][0]), "r"(a[mt][1]), "r"(a[mt][2]), "r"(a[mt][3]),
                          "r"(b[nt][0]), "r"(b[nt][1]));
        }
        if (kt + 1 < NKIT) stage(buf ^ 1);
        __syncthreads();
    }

    // epilogue: scale rows by coef, store to per-(token,rank) scratch row
    #pragma unroll
    for (int mt = 0; mt < 2; ++mt) {
        #pragma unroll
        for (int half = 0; half < 2; ++half) {
            const int r  = wm * 32 + mt * 16 + (lane >> 2) + half * 8;
            const int gm = mBase + r;
            if (gm < cnt) {
                const int   dest = d_perm_dest[e * T + gm];
                const float coef = d_perm_coef[e * T + gm];
                float* orow = d_scratch + (size_t)dest * H + nBase;
                #pragma unroll
                for (int nt = 0; nt < 8; ++nt) {
                    const int col = wn * 64 + nt * 8 + (lane & 3) * 2;
                    float2 v;
                    v.x = c[mt][nt][half * 2 + 0] * coef;
                    v.y = c[mt][nt][half * 2 + 1] * coef;
                    *(float2*)(orow + col) = v;
                }
            }
        }
    }
}

// ============================================================
// Reduce: out[t] = sum_k scratch[t*6+k] + bias[t]
__global__ void __launch_bounds__(256) reduce_kernel(float* __restrict__ out)
{
    const int gid = blockIdx.x * blockDim.x + threadIdx.x;   // float4 index
    const int t   = gid >> 8;                                // H/4 = 256 per token
    const float4* s = (const float4*)d_scratch;
    const size_t base = (size_t)t * TOPK * (H / 4) + (gid & 255);

    float4 a = s[base];
    #pragma unroll
    for (int k = 1; k < TOPK; ++k) {
        const float4 b = s[base + (size_t)k * (H / 4)];
        a.x += b.x; a.y += b.y; a.z += b.z; a.w += b.w;
    }
    const float bi = d_bias[t];
    a.x += bi; a.y += bi; a.z += bi; a.w += bi;
    ((float4*)out)[gid] = a;
}

// ============================================================
extern "C" void kernel_launch(void* const* d_in, const int* in_sizes, int n_in,
                              void* d_out, int out_size)
{
    const float* tokens = (const float*)d_in[0];   // [4,2048,1024]
    const float* rw     = (const float*)d_in[1];   // [16,1024]
    const float* rb     = (const float*)d_in[2];   // [16]
    const float* ew     = (const float*)d_in[3];   // [16,1024,1024]
    float* out = (float*)d_out;

    zero_counts_kernel<<<1, 32>>>();
    router_kernel<<<T / 128, 256>>>(tokens, rw, rb);
    dim3 g(H / BN, T / BM, E);
    moe_gemm_kernel<<<g, 256>>>(tokens, ew);
    reduce_kernel<<<(T * H / 4) / 256, 256>>>(out);
}